// round 12
// baseline (speedup 1.0000x reference)
#include <cuda_runtime.h>
#include <cuda_fp16.h>

#define W0 512
#define H0 512
#define BATCH 32
#define TH 16   // pixel rows per thread (four flat 4-row stages)
#define BLK 128

// Fused pair tables: entry e = p*256+q holds 8 halves:
//   [0..3] = 0.5 * T[p*256+q]  ("self")
//   [4..7] = 0.5 * T[q*256+p]  ("other")
__device__ uint4 g_H2[65536];
__device__ uint4 g_V2[65536];
__device__ uint4 g_D2[65536];

static __device__ __forceinline__ unsigned pack_h2(float a, float b) {
    __half2 h = __floats2half2_rn(a, b);
    return *reinterpret_cast<unsigned*>(&h);
}

// Coalesced prep: 32x32 tile of (p,q) per block; mirror tile transposed
// through smem. Triggers programmatic launch of the main kernel at entry
// so the main grid's table-independent prologue overlaps with prep.
__global__ __launch_bounds__(256) void prep_kernel(
    const float4* __restrict__ hw,
    const float4* __restrict__ dw,
    const float4* __restrict__ vw)
{
    cudaTriggerProgrammaticLaunchCompletion();

    __shared__ float4 A[32][33];
    __shared__ float4 B[32][33];

    int tb = blockIdx.z;
    const float4* src = (tb == 0) ? hw : (tb == 1) ? dw : vw;
    uint4* dst = (tb == 0) ? g_H2 : (tb == 1) ? g_D2 : g_V2;

    int p0 = blockIdx.y * 32;
    int q0 = blockIdx.x * 32;
    int tx = threadIdx.x;

#pragma unroll
    for (int r = threadIdx.y; r < 32; r += 8) {
        A[r][tx] = src[(p0 + r) * 256 + q0 + tx];
        B[r][tx] = src[(q0 + r) * 256 + p0 + tx];
    }
    __syncthreads();

#pragma unroll
    for (int r = threadIdx.y; r < 32; r += 8) {
        float4 s = A[r][tx];
        float4 o = B[tx][r];
        uint4 u;
        u.x = pack_h2(0.5f * s.x, 0.5f * s.y);
        u.y = pack_h2(0.5f * s.z, 0.5f * s.w);
        u.z = pack_h2(0.5f * o.x, 0.5f * o.y);
        u.w = pack_h2(0.5f * o.z, 0.5f * o.w);
        dst[(p0 + r) * 256 + q0 + tx] = u;
    }
}

// ---- accumulation helpers ----
static __device__ __forceinline__ void acc_fwd(float* a, unsigned x, unsigned y) {
    float2 p = __half22float2(*reinterpret_cast<__half2*>(&x));
    float2 q = __half22float2(*reinterpret_cast<__half2*>(&y));
    a[0] += p.x; a[1] += p.y; a[2] += q.x; a[3] += q.y;
}
static __device__ __forceinline__ void acc_rev(float* a, unsigned x, unsigned y) {
    float2 p = __half22float2(*reinterpret_cast<__half2*>(&x));
    float2 q = __half22float2(*reinterpret_cast<__half2*>(&y));
    a[3] += p.x; a[2] += p.y; a[1] += q.x; a[0] += q.y;
}
static __device__ __forceinline__ void acc_dl(float* a, unsigned x, unsigned y) {
    float2 p = __half22float2(*reinterpret_cast<__half2*>(&x));
    float2 q = __half22float2(*reinterpret_cast<__half2*>(&y));
    a[1] += p.x; a[3] += p.y; a[0] += q.x; a[2] += q.y;
}
static __device__ __forceinline__ void acc_ur(float* a, unsigned x, unsigned y) {
    float2 p = __half22float2(*reinterpret_cast<__half2*>(&x));
    float2 q = __half22float2(*reinterpret_cast<__half2*>(&y));
    a[2] += p.x; a[0] += p.y; a[3] += q.x; a[1] += q.y;
}

#define SITE_LOAD(P, wa, wb)                                                   \
    uint4 P##v1 = __ldg(&g_V2[__byte_perm(wa, wb, 0x4415) & 0xFFFF]);          \
    uint4 P##v2 = __ldg(&g_V2[__byte_perm(wa, wb, 0x4426) & 0xFFFF]);          \
    uint4 P##m1 = __ldg(&g_D2[__byte_perm(wa, wb, 0x4416) & 0xFFFF]);          \
    uint4 P##m2 = __ldg(&g_D2[__byte_perm(wa, wb, 0x4427) & 0xFFFF]);          \
    uint4 P##a2 = __ldg(&g_D2[__byte_perm(wa, wb, 0x4425) & 0xFFFF]);          \
    uint4 P##a3 = __ldg(&g_D2[__byte_perm(wa, wb, 0x4436) & 0xFFFF]);          \
    unsigned P##m2z = __shfl_up_sync(0xFFFFFFFFu, P##m2.z, 1);                 \
    unsigned P##m2w = __shfl_up_sync(0xFFFFFFFFu, P##m2.w, 1);                 \
    unsigned P##a3x = __shfl_up_sync(0xFFFFFFFFu, P##a3.x, 1);                 \
    unsigned P##a3y = __shfl_up_sync(0xFFFFFFFFu, P##a3.y, 1);                 \
    if (lane == 0) {                                                           \
        uint4 _m0 = __ldg(&g_D2[__byte_perm(wa, wb, 0x4405) & 0xFFFF]);        \
        uint4 _a1 = __ldg(&g_D2[__byte_perm(wa, wb, 0x4414) & 0xFFFF]);        \
        P##m2z = _m0.z; P##m2w = _m0.w; P##a3x = _a1.x; P##a3y = _a1.y;        \
    }

#define SITE_SELF(P, rp)                                                       \
    acc_fwd(rp[0], P##v1.x, P##v1.y); acc_fwd(rp[1], P##v2.x, P##v2.y);        \
    acc_fwd(rp[0], P##m1.x, P##m1.y); acc_fwd(rp[1], P##m2.x, P##m2.y);        \
    acc_dl (rp[1], P##a2.x, P##a2.y); acc_dl (rp[0], P##a3x,  P##a3y);

#define SITE_OTHER(P, rn)                                                      \
    acc_rev(rn[0], P##v1.z, P##v1.w); acc_rev(rn[1], P##v2.z, P##v2.w);        \
    acc_rev(rn[1], P##m1.z, P##m1.w); acc_rev(rn[0], P##m2z,  P##m2w);         \
    acc_ur (rn[0], P##a2.z, P##a2.w); acc_ur (rn[1], P##a3.z, P##a3.w);

#define H_ROW(rp, wa)                                                          \
    { uint4 _h1 = __ldg(&g_H2[__byte_perm(wa, 0, 0x4412)]);                    \
      uint4 _h2 = __ldg(&g_H2[__byte_perm(wa, 0, 0x4423)]);                    \
      unsigned _h2z = __shfl_up_sync(0xFFFFFFFFu, _h2.z, 1);                   \
      unsigned _h2w = __shfl_up_sync(0xFFFFFFFFu, _h2.w, 1);                   \
      if (lane == 0) {                                                         \
          uint4 _h0 = __ldg(&g_H2[__byte_perm(wa, 0, 0x4401)]);                \
          _h2z = _h0.z; _h2w = _h0.w;                                          \
      }                                                                        \
      acc_fwd(rp[0], _h1.x, _h1.y); acc_rev(rp[1], _h1.z, _h1.w);              \
      acc_fwd(rp[1], _h2.x, _h2.y); acc_rev(rp[0], _h2z,  _h2w); }

#define STORE_ROW(rp, r)                                                       \
    { unsigned _o = (unsigned)(2 * (y0 + (r))) * (2 * W0);                     \
      *reinterpret_cast<float4*>(outp + _o) =                                  \
          make_float4(rp[0][0], rp[0][1], rp[1][0], rp[1][1]);                 \
      *reinterpret_cast<float4*>(outp + _o + 2 * W0) =                         \
          make_float4(rp[0][2], rp[0][3], rp[1][2], rp[1][3]); }

struct Carry {
    unsigned v1z, v1w, v2z, v2w, m1z, m1w, m2z, m2w, a2z, a2w, a3z, a3w;
};

template<bool FIRST, bool LAST>
static __device__ __forceinline__ void stage4(
    int lane, unsigned u0, unsigned u1, unsigned u2, unsigned u3,
    unsigned u4, unsigned u5, const Carry& cin, Carry& cout,
    float* outp, int y0, int r0)
{
    float A0[2][4] = {}, A1[2][4] = {}, A2[2][4] = {}, A3[2][4] = {};

    if (FIRST) {
        SITE_LOAD(s0, u0, u1);
        SITE_OTHER(s0, A0);
    } else {
        acc_rev(A0[0], cin.v1z, cin.v1w); acc_rev(A0[1], cin.v2z, cin.v2w);
        acc_rev(A0[1], cin.m1z, cin.m1w); acc_rev(A0[0], cin.m2z, cin.m2w);
        acc_ur (A0[0], cin.a2z, cin.a2w); acc_ur (A0[1], cin.a3z, cin.a3w);
    }
    { SITE_LOAD(s1, u1, u2); SITE_SELF(s1, A0); SITE_OTHER(s1, A1); }
    H_ROW(A0, u1);
    { SITE_LOAD(s2, u2, u3); SITE_SELF(s2, A1); SITE_OTHER(s2, A2); }
    H_ROW(A1, u2);
    { SITE_LOAD(s3, u3, u4); SITE_SELF(s3, A2); SITE_OTHER(s3, A3); }
    H_ROW(A2, u3);
    {
        SITE_LOAD(s4, u4, u5);
        SITE_SELF(s4, A3);
        if (!LAST) {
            cout.v1z = s4v1.z; cout.v1w = s4v1.w;
            cout.v2z = s4v2.z; cout.v2w = s4v2.w;
            cout.m1z = s4m1.z; cout.m1w = s4m1.w;
            cout.m2z = s4m2z;  cout.m2w = s4m2w;
            cout.a2z = s4a2.z; cout.a2w = s4a2.w;
            cout.a3z = s4a3.z; cout.a3w = s4a3.w;
        }
    }
    H_ROW(A3, u4);

    STORE_ROW(A0, r0); STORE_ROW(A1, r0 + 1);
    STORE_ROW(A2, r0 + 2); STORE_ROW(A3, r0 + 3);
}

__global__ __launch_bounds__(BLK) void hdvlut_kernel(
    const int* __restrict__ img,
    float* __restrict__ out)
{
    int lane = threadIdx.x & 31;
    int x0 = (blockIdx.x * BLK + threadIdx.x) * 2;
    int y0 = blockIdx.y * TH;
    int b  = blockIdx.z;

    const int* im = img + b * (H0 * W0);
    int xs0 = max(x0 - 1, 0);
    int xs3 = min(x0 + 2, W0 - 1);

// middle two pixels via one aligned int2 load; edges scalar (clamped)
#define LOADROW(yy, dst) do {                                            \
        int _y = min(max((yy), 0), H0 - 1);                              \
        const int* _rp = im + _y * W0;                                   \
        unsigned _a0 = (unsigned)__ldg(_rp + xs0);                       \
        int2 _m = __ldg(reinterpret_cast<const int2*>(_rp + x0));        \
        unsigned _a3 = (unsigned)__ldg(_rp + xs3);                       \
        dst = _a0 | ((unsigned)_m.x << 8) | ((unsigned)_m.y << 16)       \
                  | (_a3 << 24);                                         \
    } while (0)

    float* outp = out + (size_t)b * (2 * H0) * (2 * W0) + 2 * x0;

    Carry c0, c1;

    // stage 0 image rows (table-independent) — overlaps with prep via PDL
    unsigned w0, w1, w2, w3, w4, w5;
    LOADROW(y0 - 1, w0); LOADROW(y0,     w1); LOADROW(y0 + 1, w2);
    LOADROW(y0 + 2, w3); LOADROW(y0 + 3, w4); LOADROW(y0 + 4, w5);

    // Wait for prep_kernel's table writes to be visible before any gather.
    cudaGridDependencySynchronize();

    stage4<true, false>(lane, w0, w1, w2, w3, w4, w5, c0, c0, outp, y0, 0);

    // stage 1: rows 4..7
    unsigned w6, w7, w8, w9;
    LOADROW(y0 + 5, w6); LOADROW(y0 + 6, w7);
    LOADROW(y0 + 7, w8); LOADROW(y0 + 8, w9);
    stage4<false, false>(lane, w4, w5, w6, w7, w8, w9, c0, c1, outp, y0, 4);

    // stage 2: rows 8..11
    unsigned wA, wB, wC, wD;
    LOADROW(y0 + 9,  wA); LOADROW(y0 + 10, wB);
    LOADROW(y0 + 11, wC); LOADROW(y0 + 12, wD);
    stage4<false, false>(lane, w8, w9, wA, wB, wC, wD, c1, c0, outp, y0, 8);

    // stage 3: rows 12..15
    unsigned wE, wF, wG, wH;
    LOADROW(y0 + 13, wE); LOADROW(y0 + 14, wF);
    LOADROW(y0 + 15, wG); LOADROW(y0 + 16, wH);
    stage4<false, true>(lane, wC, wD, wE, wF, wG, wH, c0, c1, outp, y0, 12);

#undef LOADROW
}

extern "C" void kernel_launch(void* const* d_in, const int* in_sizes, int n_in,
                              void* d_out, int out_size)
{
    const int*    img = (const int*)d_in[0];
    const float4* hw  = (const float4*)d_in[1];
    const float4* dw  = (const float4*)d_in[2];
    const float4* vw  = (const float4*)d_in[3];
    float*        out = (float*)d_out;

    // primary: table prep (plain launch)
    dim3 pblock(32, 8, 1);
    dim3 pgrid(8, 8, 3);
    prep_kernel<<<pgrid, pblock>>>(hw, dw, vw);

    // secondary: main kernel with programmatic dependent launch — launches
    // while prep is still running; gated internally by
    // cudaGridDependencySynchronize() before the first table gather.
    cudaLaunchConfig_t cfg = {};
    cfg.gridDim  = dim3((W0 / 2) / BLK, H0 / TH, BATCH);
    cfg.blockDim = dim3(BLK, 1, 1);
    cfg.dynamicSmemBytes = 0;
    cfg.stream = 0;
    cudaLaunchAttribute attrs[1];
    attrs[0].id = cudaLaunchAttributeProgrammaticStreamSerialization;
    attrs[0].val.programmaticStreamSerializationAllowed = 1;
    cfg.attrs = attrs;
    cfg.numAttrs = 1;
    cudaLaunchKernelEx(&cfg, hdvlut_kernel, img, out);
}

// round 13
// speedup vs baseline: 1.8605x; 1.8605x over previous
#include <cuda_runtime.h>
#include <cuda_fp16.h>

#define W0 512
#define H0 512
#define BATCH 32
#define TH 16   // pixel rows per thread (four flat 4-row stages)
#define BLK 128

// Fused pair tables: entry e = p*256+q holds 8 halves:
//   [0..3] = 0.5 * T[p*256+q]  ("self")
//   [4..7] = 0.5 * T[q*256+p]  ("other")
__device__ uint4 g_H2[65536];
__device__ uint4 g_V2[65536];
__device__ uint4 g_D2[65536];

static __device__ __forceinline__ unsigned pack_h2(float a, float b) {
    __half2 h = __floats2half2_rn(a, b);
    return *reinterpret_cast<unsigned*>(&h);
}

// Coalesced prep: 32x32 tile of (p,q) per block; mirror tile transposed
// through smem so both halves come from coalesced loads.
__global__ __launch_bounds__(256) void prep_kernel(
    const float4* __restrict__ hw,
    const float4* __restrict__ dw,
    const float4* __restrict__ vw)
{
    __shared__ float4 A[32][33];
    __shared__ float4 B[32][33];

    int tb = blockIdx.z;
    const float4* src = (tb == 0) ? hw : (tb == 1) ? dw : vw;
    uint4* dst = (tb == 0) ? g_H2 : (tb == 1) ? g_D2 : g_V2;

    int p0 = blockIdx.y * 32;
    int q0 = blockIdx.x * 32;
    int tx = threadIdx.x;

#pragma unroll
    for (int r = threadIdx.y; r < 32; r += 8) {
        A[r][tx] = src[(p0 + r) * 256 + q0 + tx];
        B[r][tx] = src[(q0 + r) * 256 + p0 + tx];
    }
    __syncthreads();

#pragma unroll
    for (int r = threadIdx.y; r < 32; r += 8) {
        float4 s = A[r][tx];
        float4 o = B[tx][r];
        uint4 u;
        u.x = pack_h2(0.5f * s.x, 0.5f * s.y);
        u.y = pack_h2(0.5f * s.z, 0.5f * s.w);
        u.z = pack_h2(0.5f * o.x, 0.5f * o.y);
        u.w = pack_h2(0.5f * o.z, 0.5f * o.w);
        dst[(p0 + r) * 256 + q0 + tx] = u;
    }
}

// ---- accumulation helpers ----
static __device__ __forceinline__ void acc_fwd(float* a, unsigned x, unsigned y) {
    float2 p = __half22float2(*reinterpret_cast<__half2*>(&x));
    float2 q = __half22float2(*reinterpret_cast<__half2*>(&y));
    a[0] += p.x; a[1] += p.y; a[2] += q.x; a[3] += q.y;
}
static __device__ __forceinline__ void acc_rev(float* a, unsigned x, unsigned y) {
    float2 p = __half22float2(*reinterpret_cast<__half2*>(&x));
    float2 q = __half22float2(*reinterpret_cast<__half2*>(&y));
    a[3] += p.x; a[2] += p.y; a[1] += q.x; a[0] += q.y;
}
static __device__ __forceinline__ void acc_dl(float* a, unsigned x, unsigned y) {
    float2 p = __half22float2(*reinterpret_cast<__half2*>(&x));
    float2 q = __half22float2(*reinterpret_cast<__half2*>(&y));
    a[1] += p.x; a[3] += p.y; a[0] += q.x; a[2] += q.y;
}
static __device__ __forceinline__ void acc_ur(float* a, unsigned x, unsigned y) {
    float2 p = __half22float2(*reinterpret_cast<__half2*>(&x));
    float2 q = __half22float2(*reinterpret_cast<__half2*>(&y));
    a[2] += p.x; a[0] += p.y; a[3] += q.x; a[1] += q.y;
}

#define SITE_LOAD(P, wa, wb)                                                   \
    uint4 P##v1 = __ldg(&g_V2[__byte_perm(wa, wb, 0x4415) & 0xFFFF]);          \
    uint4 P##v2 = __ldg(&g_V2[__byte_perm(wa, wb, 0x4426) & 0xFFFF]);          \
    uint4 P##m1 = __ldg(&g_D2[__byte_perm(wa, wb, 0x4416) & 0xFFFF]);          \
    uint4 P##m2 = __ldg(&g_D2[__byte_perm(wa, wb, 0x4427) & 0xFFFF]);          \
    uint4 P##a2 = __ldg(&g_D2[__byte_perm(wa, wb, 0x4425) & 0xFFFF]);          \
    uint4 P##a3 = __ldg(&g_D2[__byte_perm(wa, wb, 0x4436) & 0xFFFF]);          \
    unsigned P##m2z = __shfl_up_sync(0xFFFFFFFFu, P##m2.z, 1);                 \
    unsigned P##m2w = __shfl_up_sync(0xFFFFFFFFu, P##m2.w, 1);                 \
    unsigned P##a3x = __shfl_up_sync(0xFFFFFFFFu, P##a3.x, 1);                 \
    unsigned P##a3y = __shfl_up_sync(0xFFFFFFFFu, P##a3.y, 1);                 \
    if (lane == 0) {                                                           \
        uint4 _m0 = __ldg(&g_D2[__byte_perm(wa, wb, 0x4405) & 0xFFFF]);        \
        uint4 _a1 = __ldg(&g_D2[__byte_perm(wa, wb, 0x4414) & 0xFFFF]);        \
        P##m2z = _m0.z; P##m2w = _m0.w; P##a3x = _a1.x; P##a3y = _a1.y;        \
    }

#define SITE_SELF(P, rp)                                                       \
    acc_fwd(rp[0], P##v1.x, P##v1.y); acc_fwd(rp[1], P##v2.x, P##v2.y);        \
    acc_fwd(rp[0], P##m1.x, P##m1.y); acc_fwd(rp[1], P##m2.x, P##m2.y);        \
    acc_dl (rp[1], P##a2.x, P##a2.y); acc_dl (rp[0], P##a3x,  P##a3y);

#define SITE_OTHER(P, rn)                                                      \
    acc_rev(rn[0], P##v1.z, P##v1.w); acc_rev(rn[1], P##v2.z, P##v2.w);        \
    acc_rev(rn[1], P##m1.z, P##m1.w); acc_rev(rn[0], P##m2z,  P##m2w);         \
    acc_ur (rn[0], P##a2.z, P##a2.w); acc_ur (rn[1], P##a3.z, P##a3.w);

#define H_ROW(rp, wa)                                                          \
    { uint4 _h1 = __ldg(&g_H2[__byte_perm(wa, 0, 0x4412)]);                    \
      uint4 _h2 = __ldg(&g_H2[__byte_perm(wa, 0, 0x4423)]);                    \
      unsigned _h2z = __shfl_up_sync(0xFFFFFFFFu, _h2.z, 1);                   \
      unsigned _h2w = __shfl_up_sync(0xFFFFFFFFu, _h2.w, 1);                   \
      if (lane == 0) {                                                         \
          uint4 _h0 = __ldg(&g_H2[__byte_perm(wa, 0, 0x4401)]);                \
          _h2z = _h0.z; _h2w = _h0.w;                                          \
      }                                                                        \
      acc_fwd(rp[0], _h1.x, _h1.y); acc_rev(rp[1], _h1.z, _h1.w);              \
      acc_fwd(rp[1], _h2.x, _h2.y); acc_rev(rp[0], _h2z,  _h2w); }

// streaming (evict-first) output stores: output is write-once, keep tables
// resident in L2 instead.
#define STORE_ROW(rp, r)                                                       \
    { unsigned _o = (unsigned)(2 * (y0 + (r))) * (2 * W0);                     \
      __stcs(reinterpret_cast<float4*>(outp + _o),                             \
             make_float4(rp[0][0], rp[0][1], rp[1][0], rp[1][1]));             \
      __stcs(reinterpret_cast<float4*>(outp + _o + 2 * W0),                    \
             make_float4(rp[0][2], rp[0][3], rp[1][2], rp[1][3])); }

struct Carry {
    unsigned v1z, v1w, v2z, v2w, m1z, m1w, m2z, m2w, a2z, a2w, a3z, a3w;
};

template<bool FIRST, bool LAST>
static __device__ __forceinline__ void stage4(
    int lane, unsigned u0, unsigned u1, unsigned u2, unsigned u3,
    unsigned u4, unsigned u5, const Carry& cin, Carry& cout,
    float* outp, int y0, int r0)
{
    float A0[2][4] = {}, A1[2][4] = {}, A2[2][4] = {}, A3[2][4] = {};

    if (FIRST) {
        SITE_LOAD(s0, u0, u1);
        SITE_OTHER(s0, A0);
    } else {
        acc_rev(A0[0], cin.v1z, cin.v1w); acc_rev(A0[1], cin.v2z, cin.v2w);
        acc_rev(A0[1], cin.m1z, cin.m1w); acc_rev(A0[0], cin.m2z, cin.m2w);
        acc_ur (A0[0], cin.a2z, cin.a2w); acc_ur (A0[1], cin.a3z, cin.a3w);
    }
    { SITE_LOAD(s1, u1, u2); SITE_SELF(s1, A0); SITE_OTHER(s1, A1); }
    H_ROW(A0, u1);
    { SITE_LOAD(s2, u2, u3); SITE_SELF(s2, A1); SITE_OTHER(s2, A2); }
    H_ROW(A1, u2);
    { SITE_LOAD(s3, u3, u4); SITE_SELF(s3, A2); SITE_OTHER(s3, A3); }
    H_ROW(A2, u3);
    {
        SITE_LOAD(s4, u4, u5);
        SITE_SELF(s4, A3);
        if (!LAST) {
            cout.v1z = s4v1.z; cout.v1w = s4v1.w;
            cout.v2z = s4v2.z; cout.v2w = s4v2.w;
            cout.m1z = s4m1.z; cout.m1w = s4m1.w;
            cout.m2z = s4m2z;  cout.m2w = s4m2w;
            cout.a2z = s4a2.z; cout.a2w = s4a2.w;
            cout.a3z = s4a3.z; cout.a3w = s4a3.w;
        }
    }
    H_ROW(A3, u4);

    STORE_ROW(A0, r0); STORE_ROW(A1, r0 + 1);
    STORE_ROW(A2, r0 + 2); STORE_ROW(A3, r0 + 3);
}

__global__ __launch_bounds__(BLK) void hdvlut_kernel(
    const int* __restrict__ img,
    float* __restrict__ out)
{
    int lane = threadIdx.x & 31;
    int x0 = (blockIdx.x * BLK + threadIdx.x) * 2;
    int y0 = blockIdx.y * TH;
    int b  = blockIdx.z;

    const int* im = img + b * (H0 * W0);
    int xs0 = max(x0 - 1, 0);
    int xs3 = min(x0 + 2, W0 - 1);

// middle two pixels via one aligned int2 load; edges scalar (clamped)
#define LOADROW(yy, dst) do {                                            \
        int _y = min(max((yy), 0), H0 - 1);                              \
        const int* _rp = im + _y * W0;                                   \
        unsigned _a0 = (unsigned)__ldg(_rp + xs0);                       \
        int2 _m = __ldg(reinterpret_cast<const int2*>(_rp + x0));        \
        unsigned _a3 = (unsigned)__ldg(_rp + xs3);                       \
        dst = _a0 | ((unsigned)_m.x << 8) | ((unsigned)_m.y << 16)       \
                  | (_a3 << 24);                                         \
    } while (0)

    float* outp = out + (size_t)b * (2 * H0) * (2 * W0) + 2 * x0;

    Carry c0, c1;

    // stage 0: rows 0..3
    unsigned w0, w1, w2, w3, w4, w5;
    LOADROW(y0 - 1, w0); LOADROW(y0,     w1); LOADROW(y0 + 1, w2);
    LOADROW(y0 + 2, w3); LOADROW(y0 + 3, w4); LOADROW(y0 + 4, w5);
    stage4<true, false>(lane, w0, w1, w2, w3, w4, w5, c0, c0, outp, y0, 0);

    // stage 1: rows 4..7
    unsigned w6, w7, w8, w9;
    LOADROW(y0 + 5, w6); LOADROW(y0 + 6, w7);
    LOADROW(y0 + 7, w8); LOADROW(y0 + 8, w9);
    stage4<false, false>(lane, w4, w5, w6, w7, w8, w9, c0, c1, outp, y0, 4);

    // stage 2: rows 8..11
    unsigned wA, wB, wC, wD;
    LOADROW(y0 + 9,  wA); LOADROW(y0 + 10, wB);
    LOADROW(y0 + 11, wC); LOADROW(y0 + 12, wD);
    stage4<false, false>(lane, w8, w9, wA, wB, wC, wD, c1, c0, outp, y0, 8);

    // stage 3: rows 12..15
    unsigned wE, wF, wG, wH;
    LOADROW(y0 + 13, wE); LOADROW(y0 + 14, wF);
    LOADROW(y0 + 15, wG); LOADROW(y0 + 16, wH);
    stage4<false, true>(lane, wC, wD, wE, wF, wG, wH, c0, c1, outp, y0, 12);

#undef LOADROW
}

extern "C" void kernel_launch(void* const* d_in, const int* in_sizes, int n_in,
                              void* d_out, int out_size)
{
    const int*    img = (const int*)d_in[0];
    const float4* hw  = (const float4*)d_in[1];
    const float4* dw  = (const float4*)d_in[2];
    const float4* vw  = (const float4*)d_in[3];
    float*        out = (float*)d_out;

    dim3 pblock(32, 8, 1);
    dim3 pgrid(8, 8, 3);
    prep_kernel<<<pgrid, pblock>>>(hw, dw, vw);

    dim3 block(BLK, 1, 1);
    dim3 grid((W0 / 2) / BLK, H0 / TH, BATCH);
    hdvlut_kernel<<<grid, block>>>(img, out);
}

// round 14
// speedup vs baseline: 1.8691x; 1.0046x over previous
#include <cuda_runtime.h>
#include <cuda_fp16.h>

#define W0 512
#define H0 512
#define BATCH 32
#define TH 16   // pixel rows per thread (four flat 4-row stages)
#define BLK 128

// Fused pair tables: entry e = p*256+q holds 8 halves:
//   [0..3] = 0.5 * T[p*256+q]  ("self")
//   [4..7] = 0.5 * T[q*256+p]  ("other")
__device__ uint4 g_H2[65536];
__device__ uint4 g_V2[65536];
__device__ uint4 g_D2[65536];

static __device__ __forceinline__ unsigned pack_h2(float a, float b) {
    __half2 h = __floats2half2_rn(a, b);
    return *reinterpret_cast<unsigned*>(&h);
}

// Coalesced prep: 32x32 tile of (p,q) per block; mirror tile transposed
// through smem. 512 threads/block for latency hiding; streaming loads
// (sources are read exactly twice, then dead).
__global__ __launch_bounds__(512) void prep_kernel(
    const float4* __restrict__ hw,
    const float4* __restrict__ dw,
    const float4* __restrict__ vw)
{
    __shared__ float4 A[32][33];
    __shared__ float4 B[32][33];

    int tb = blockIdx.z;
    const float4* src = (tb == 0) ? hw : (tb == 1) ? dw : vw;
    uint4* dst = (tb == 0) ? g_H2 : (tb == 1) ? g_D2 : g_V2;

    int p0 = blockIdx.y * 32;
    int q0 = blockIdx.x * 32;
    int tx = threadIdx.x;

#pragma unroll
    for (int r = threadIdx.y; r < 32; r += 16) {
        A[r][tx] = __ldcs(&src[(p0 + r) * 256 + q0 + tx]);
        B[r][tx] = __ldcs(&src[(q0 + r) * 256 + p0 + tx]);
    }
    __syncthreads();

#pragma unroll
    for (int r = threadIdx.y; r < 32; r += 16) {
        float4 s = A[r][tx];
        float4 o = B[tx][r];
        uint4 u;
        u.x = pack_h2(0.5f * s.x, 0.5f * s.y);
        u.y = pack_h2(0.5f * s.z, 0.5f * s.w);
        u.z = pack_h2(0.5f * o.x, 0.5f * o.y);
        u.w = pack_h2(0.5f * o.z, 0.5f * o.w);
        dst[(p0 + r) * 256 + q0 + tx] = u;
    }
}

// ---- accumulation helpers ----
static __device__ __forceinline__ void acc_fwd(float* a, unsigned x, unsigned y) {
    float2 p = __half22float2(*reinterpret_cast<__half2*>(&x));
    float2 q = __half22float2(*reinterpret_cast<__half2*>(&y));
    a[0] += p.x; a[1] += p.y; a[2] += q.x; a[3] += q.y;
}
static __device__ __forceinline__ void acc_rev(float* a, unsigned x, unsigned y) {
    float2 p = __half22float2(*reinterpret_cast<__half2*>(&x));
    float2 q = __half22float2(*reinterpret_cast<__half2*>(&y));
    a[3] += p.x; a[2] += p.y; a[1] += q.x; a[0] += q.y;
}
static __device__ __forceinline__ void acc_dl(float* a, unsigned x, unsigned y) {
    float2 p = __half22float2(*reinterpret_cast<__half2*>(&x));
    float2 q = __half22float2(*reinterpret_cast<__half2*>(&y));
    a[1] += p.x; a[3] += p.y; a[0] += q.x; a[2] += q.y;
}
static __device__ __forceinline__ void acc_ur(float* a, unsigned x, unsigned y) {
    float2 p = __half22float2(*reinterpret_cast<__half2*>(&x));
    float2 q = __half22float2(*reinterpret_cast<__half2*>(&y));
    a[2] += p.x; a[0] += p.y; a[3] += q.x; a[1] += q.y;
}

#define SITE_LOAD(P, wa, wb)                                                   \
    uint4 P##v1 = __ldg(&g_V2[__byte_perm(wa, wb, 0x4415) & 0xFFFF]);          \
    uint4 P##v2 = __ldg(&g_V2[__byte_perm(wa, wb, 0x4426) & 0xFFFF]);          \
    uint4 P##m1 = __ldg(&g_D2[__byte_perm(wa, wb, 0x4416) & 0xFFFF]);          \
    uint4 P##m2 = __ldg(&g_D2[__byte_perm(wa, wb, 0x4427) & 0xFFFF]);          \
    uint4 P##a2 = __ldg(&g_D2[__byte_perm(wa, wb, 0x4425) & 0xFFFF]);          \
    uint4 P##a3 = __ldg(&g_D2[__byte_perm(wa, wb, 0x4436) & 0xFFFF]);          \
    unsigned P##m2z = __shfl_up_sync(0xFFFFFFFFu, P##m2.z, 1);                 \
    unsigned P##m2w = __shfl_up_sync(0xFFFFFFFFu, P##m2.w, 1);                 \
    unsigned P##a3x = __shfl_up_sync(0xFFFFFFFFu, P##a3.x, 1);                 \
    unsigned P##a3y = __shfl_up_sync(0xFFFFFFFFu, P##a3.y, 1);                 \
    if (lane == 0) {                                                           \
        uint4 _m0 = __ldg(&g_D2[__byte_perm(wa, wb, 0x4405) & 0xFFFF]);        \
        uint4 _a1 = __ldg(&g_D2[__byte_perm(wa, wb, 0x4414) & 0xFFFF]);        \
        P##m2z = _m0.z; P##m2w = _m0.w; P##a3x = _a1.x; P##a3y = _a1.y;        \
    }

#define SITE_SELF(P, rp)                                                       \
    acc_fwd(rp[0], P##v1.x, P##v1.y); acc_fwd(rp[1], P##v2.x, P##v2.y);        \
    acc_fwd(rp[0], P##m1.x, P##m1.y); acc_fwd(rp[1], P##m2.x, P##m2.y);        \
    acc_dl (rp[1], P##a2.x, P##a2.y); acc_dl (rp[0], P##a3x,  P##a3y);

#define SITE_OTHER(P, rn)                                                      \
    acc_rev(rn[0], P##v1.z, P##v1.w); acc_rev(rn[1], P##v2.z, P##v2.w);        \
    acc_rev(rn[1], P##m1.z, P##m1.w); acc_rev(rn[0], P##m2z,  P##m2w);         \
    acc_ur (rn[0], P##a2.z, P##a2.w); acc_ur (rn[1], P##a3.z, P##a3.w);

#define H_ROW(rp, wa)                                                          \
    { uint4 _h1 = __ldg(&g_H2[__byte_perm(wa, 0, 0x4412)]);                    \
      uint4 _h2 = __ldg(&g_H2[__byte_perm(wa, 0, 0x4423)]);                    \
      unsigned _h2z = __shfl_up_sync(0xFFFFFFFFu, _h2.z, 1);                   \
      unsigned _h2w = __shfl_up_sync(0xFFFFFFFFu, _h2.w, 1);                   \
      if (lane == 0) {                                                         \
          uint4 _h0 = __ldg(&g_H2[__byte_perm(wa, 0, 0x4401)]);                \
          _h2z = _h0.z; _h2w = _h0.w;                                          \
      }                                                                        \
      acc_fwd(rp[0], _h1.x, _h1.y); acc_rev(rp[1], _h1.z, _h1.w);              \
      acc_fwd(rp[1], _h2.x, _h2.y); acc_rev(rp[0], _h2z,  _h2w); }

// streaming (evict-first) output stores: output is write-once, keep tables
// resident in L2 instead.
#define STORE_ROW(rp, r)                                                       \
    { unsigned _o = (unsigned)(2 * (y0 + (r))) * (2 * W0);                     \
      __stcs(reinterpret_cast<float4*>(outp + _o),                             \
             make_float4(rp[0][0], rp[0][1], rp[1][0], rp[1][1]));             \
      __stcs(reinterpret_cast<float4*>(outp + _o + 2 * W0),                    \
             make_float4(rp[0][2], rp[0][3], rp[1][2], rp[1][3])); }

struct Carry {
    unsigned v1z, v1w, v2z, v2w, m1z, m1w, m2z, m2w, a2z, a2w, a3z, a3w;
};

template<bool FIRST, bool LAST>
static __device__ __forceinline__ void stage4(
    int lane, unsigned u0, unsigned u1, unsigned u2, unsigned u3,
    unsigned u4, unsigned u5, const Carry& cin, Carry& cout,
    float* outp, int y0, int r0)
{
    float A0[2][4] = {}, A1[2][4] = {}, A2[2][4] = {}, A3[2][4] = {};

    if (FIRST) {
        SITE_LOAD(s0, u0, u1);
        SITE_OTHER(s0, A0);
    } else {
        acc_rev(A0[0], cin.v1z, cin.v1w); acc_rev(A0[1], cin.v2z, cin.v2w);
        acc_rev(A0[1], cin.m1z, cin.m1w); acc_rev(A0[0], cin.m2z, cin.m2w);
        acc_ur (A0[0], cin.a2z, cin.a2w); acc_ur (A0[1], cin.a3z, cin.a3w);
    }
    { SITE_LOAD(s1, u1, u2); SITE_SELF(s1, A0); SITE_OTHER(s1, A1); }
    H_ROW(A0, u1);
    { SITE_LOAD(s2, u2, u3); SITE_SELF(s2, A1); SITE_OTHER(s2, A2); }
    H_ROW(A1, u2);
    { SITE_LOAD(s3, u3, u4); SITE_SELF(s3, A2); SITE_OTHER(s3, A3); }
    H_ROW(A2, u3);
    {
        SITE_LOAD(s4, u4, u5);
        SITE_SELF(s4, A3);
        if (!LAST) {
            cout.v1z = s4v1.z; cout.v1w = s4v1.w;
            cout.v2z = s4v2.z; cout.v2w = s4v2.w;
            cout.m1z = s4m1.z; cout.m1w = s4m1.w;
            cout.m2z = s4m2z;  cout.m2w = s4m2w;
            cout.a2z = s4a2.z; cout.a2w = s4a2.w;
            cout.a3z = s4a3.z; cout.a3w = s4a3.w;
        }
    }
    H_ROW(A3, u4);

    STORE_ROW(A0, r0); STORE_ROW(A1, r0 + 1);
    STORE_ROW(A2, r0 + 2); STORE_ROW(A3, r0 + 3);
}

__global__ __launch_bounds__(BLK) void hdvlut_kernel(
    const int* __restrict__ img,
    float* __restrict__ out)
{
    int lane = threadIdx.x & 31;
    int x0 = (blockIdx.x * BLK + threadIdx.x) * 2;
    int y0 = blockIdx.y * TH;
    int b  = blockIdx.z;

    const int* im = img + b * (H0 * W0);
    int xs0 = max(x0 - 1, 0);
    int xs3 = min(x0 + 2, W0 - 1);

// middle two pixels via one aligned int2 load; edges scalar (clamped)
#define LOADROW(yy, dst) do {                                            \
        int _y = min(max((yy), 0), H0 - 1);                              \
        const int* _rp = im + _y * W0;                                   \
        unsigned _a0 = (unsigned)__ldg(_rp + xs0);                       \
        int2 _m = __ldg(reinterpret_cast<const int2*>(_rp + x0));        \
        unsigned _a3 = (unsigned)__ldg(_rp + xs3);                       \
        dst = _a0 | ((unsigned)_m.x << 8) | ((unsigned)_m.y << 16)       \
                  | (_a3 << 24);                                         \
    } while (0)

    float* outp = out + (size_t)b * (2 * H0) * (2 * W0) + 2 * x0;

    Carry c0, c1;

    // stage 0: rows 0..3
    unsigned w0, w1, w2, w3, w4, w5;
    LOADROW(y0 - 1, w0); LOADROW(y0,     w1); LOADROW(y0 + 1, w2);
    LOADROW(y0 + 2, w3); LOADROW(y0 + 3, w4); LOADROW(y0 + 4, w5);
    stage4<true, false>(lane, w0, w1, w2, w3, w4, w5, c0, c0, outp, y0, 0);

    // stage 1: rows 4..7
    unsigned w6, w7, w8, w9;
    LOADROW(y0 + 5, w6); LOADROW(y0 + 6, w7);
    LOADROW(y0 + 7, w8); LOADROW(y0 + 8, w9);
    stage4<false, false>(lane, w4, w5, w6, w7, w8, w9, c0, c1, outp, y0, 4);

    // stage 2: rows 8..11
    unsigned wA, wB, wC, wD;
    LOADROW(y0 + 9,  wA); LOADROW(y0 + 10, wB);
    LOADROW(y0 + 11, wC); LOADROW(y0 + 12, wD);
    stage4<false, false>(lane, w8, w9, wA, wB, wC, wD, c1, c0, outp, y0, 8);

    // stage 3: rows 12..15
    unsigned wE, wF, wG, wH;
    LOADROW(y0 + 13, wE); LOADROW(y0 + 14, wF);
    LOADROW(y0 + 15, wG); LOADROW(y0 + 16, wH);
    stage4<false, true>(lane, wC, wD, wE, wF, wG, wH, c0, c1, outp, y0, 12);

#undef LOADROW
}

extern "C" void kernel_launch(void* const* d_in, const int* in_sizes, int n_in,
                              void* d_out, int out_size)
{
    const int*    img = (const int*)d_in[0];
    const float4* hw  = (const float4*)d_in[1];
    const float4* dw  = (const float4*)d_in[2];
    const float4* vw  = (const float4*)d_in[3];
    float*        out = (float*)d_out;

    dim3 pblock(32, 16, 1);
    dim3 pgrid(8, 8, 3);
    prep_kernel<<<pgrid, pblock>>>(hw, dw, vw);

    dim3 block(BLK, 1, 1);
    dim3 grid((W0 / 2) / BLK, H0 / TH, BATCH);
    hdvlut_kernel<<<grid, block>>>(img, out);
}